// round 9
// baseline (speedup 1.0000x reference)
#include <cuda_runtime.h>
#include <cuda_fp16.h>
#include <math_constants.h>
#include <cstdint>

// KNN screen-then-refine, round 9 = round-7 winner + threshold fast-path +
// single barrier per chunk (register-safe: acc[4][4], CTILE=64).
//  K2: 1-pass fp16 mma screen, QTILE=128 x CTILE=64, warp tile 16q x 32c,
//      approx top-32 per (query, strip), 8 strips/query.
//  K3: exact fp32 refine of 256 survivors -> top-32 -> mean(y).
#define DDIM      128
#define QTILE     128
#define CTILE     64
#define SPLITS    4
#define NPAD      100352
#define PER_SPLIT (NPAD / SPLITS)      // 25088
#define CHUNKS    (PER_SPLIT / CTILE)  // 392
#define NSTRIP    8                    // 4 splits * 2 c-strips
#define KSEL      32
#define QMAX      4096
#define NTHR      512

#define QSTR      136                  // padded row stride in halfs
#define QS_OFF    0                    // 128*136*2 = 34816
#define XS_OFF    34816                // 2 bufs * 64*136*2 = 34816
#define XBUF_SZ   17408
#define TSQ_OFF   69632                // 2 * 256
#define STAGE_OFF 70144                // 16 warps * 16*33*4 = 33792
#define SM_TOTAL  103936

__device__ __align__(16) __half g_xh[(size_t)NPAD * DDIM];
__device__ __align__(16) float  g_tsq[NPAD];
__device__ int g_idx[QMAX * NSTRIP * KSEL];

__device__ __forceinline__ uint32_t smem_u32(const void* p) {
    uint32_t a;
    asm("{ .reg .u64 t; cvta.to.shared.u64 t, %1; cvt.u32.u64 %0, t; }" : "=r"(a) : "l"(p));
    return a;
}
#define CPA16(dst, src) \
    asm volatile("cp.async.cg.shared.global [%0], [%1], 16;" :: "r"(dst), "l"(src))
#define CPA_COMMIT() asm volatile("cp.async.commit_group;" ::: "memory")

__device__ __forceinline__ void ldsm4(uint32_t* r, uint32_t a) {
    asm volatile("ldmatrix.sync.aligned.m8n8.x4.shared.b16 {%0,%1,%2,%3}, [%4];"
                 : "=r"(r[0]), "=r"(r[1]), "=r"(r[2]), "=r"(r[3]) : "r"(a));
}
__device__ __forceinline__ void mma16816(float* d, const uint32_t* a,
                                         uint32_t b0, uint32_t b1) {
    asm volatile("mma.sync.aligned.m16n8k16.row.col.f32.f16.f16.f32 "
                 "{%0,%1,%2,%3}, {%4,%5,%6,%7}, {%8,%9}, {%0,%1,%2,%3};"
                 : "+f"(d[0]), "+f"(d[1]), "+f"(d[2]), "+f"(d[3])
                 : "r"(a[0]), "r"(a[1]), "r"(a[2]), "r"(a[3]), "r"(b0), "r"(b1));
}
__device__ __forceinline__ uint32_t pkh(__half a, __half b) {
    __half2 t = __halves2half2(a, b);
    return *reinterpret_cast<uint32_t*>(&t);
}

// ---------------------------------------------------------------- kernel 1
__global__ void split_kernel(const float* __restrict__ X, int n) {
    int row  = blockIdx.x * 8 + (threadIdx.x >> 5);
    int lane = threadIdx.x & 31;
    if (row >= NPAD) return;
    size_t base = (size_t)row * DDIM + lane * 4;
    if (row < n) {
        float4 v = reinterpret_cast<const float4*>(X + (size_t)row * DDIM)[lane];
        float ss = v.x * v.x + v.y * v.y + v.z * v.z + v.w * v.w;
        #pragma unroll
        for (int o = 16; o; o >>= 1) ss += __shfl_xor_sync(0xffffffffu, ss, o);
        if (lane == 0) g_tsq[row] = ss;
        *reinterpret_cast<uint2*>(g_xh + base) =
            make_uint2(pkh(__float2half_rn(v.x), __float2half_rn(v.y)),
                       pkh(__float2half_rn(v.z), __float2half_rn(v.w)));
    } else {
        if (lane == 0) g_tsq[row] = CUDART_INF_F;
        *reinterpret_cast<uint2*>(g_xh + base) = make_uint2(0u, 0u);
    }
}

// ---------------------------------------------------------------- loader
// 64 rows * 256B/row = 1024 x 16B transfers -> 2 per thread; + tsq 256B.
__device__ __forceinline__ void load_chunk(uint32_t sb, int cb, int buf, int tid) {
    #pragma unroll
    for (int t = 0; t < 2; t++) {
        int idx = t * NTHR + tid;
        int row = idx >> 4, c16 = idx & 15;
        const char* sp = reinterpret_cast<const char*>(
            g_xh + (size_t)(cb + row) * DDIM) + c16 * 16;
        CPA16(sb + XS_OFF + buf * XBUF_SZ + (uint32_t)(row * QSTR * 2 + c16 * 16), sp);
    }
    if (tid < 16) {
        const char* tp = reinterpret_cast<const char*>(g_tsq + cb) + tid * 16;
        CPA16(sb + TSQ_OFF + buf * 256 + tid * 16, tp);
    }
    CPA_COMMIT();
}

// ---------------------------------------------------------------- kernel 2
__global__ void __launch_bounds__(NTHR, 1)
knn_main(const float* __restrict__ Qm, int q_total) {
    extern __shared__ char smem[];
    uint32_t sb = smem_u32(smem);
    const int tid  = threadIdx.x;
    const int lane = tid & 31;
    const int warp = tid >> 5;
    const int wm   = warp >> 1;          // 0..7 : q strip of 16
    const int wn   = warp & 1;           // 0..1 : c strip of 32
    const int split = blockIdx.y;
    const int qbase = blockIdx.x * QTILE;
    const int sbase = split * PER_SPLIT;

    load_chunk(sb, sbase, 0, tid);       // chunk 0 in flight

    // Q (-2x, fp16) -> smem
    __half* qs = reinterpret_cast<__half*>(smem + QS_OFF);
    for (int i = tid; i < QTILE * DDIM; i += NTHR) {
        int row = i >> 7, k = i & 127;
        int q = qbase + row; if (q >= q_total) q = q_total - 1;
        qs[row * QSTR + k] = __float2half_rn(-2.f * Qm[(size_t)q * DDIM + k]);
    }

    float ld[16]; int li[16];
    #pragma unroll
    for (int j = 0; j < 16; j++) { ld[j] = CUDART_INF_F; li[j] = 0; }
    float thrA = CUDART_INF_F, thrB = CUDART_INF_F;   // rows r0, r0+8

    const int r0 = lane >> 2;
    const uint32_t a_off = sb + QS_OFF
        + (uint32_t)((wm * 16 + (lane & 15)) * QSTR + (lane >> 4) * 8) * 2;
    const uint32_t b_off0 = (uint32_t)((wn * 32 + (lane & 15)) * QSTR + (lane >> 4) * 8) * 2;
    const uint32_t b_off1 = b_off0 + (uint32_t)(16 * QSTR * 2);
    float* stg = reinterpret_cast<float*>(smem + STAGE_OFF) + warp * (16 * 33);

    for (int i = 0; i < CHUNKS; i++) {
        const int cur = i & 1, nb = cur ^ 1;
        asm volatile("cp.async.wait_group 0;" ::: "memory");
        __syncthreads();                 // buf[cur] ready; buf[nb] drained
        if (i + 1 < CHUNKS) load_chunk(sb, sbase + (i + 1) * CTILE, nb, tid);

        float acc[4][4];
        #pragma unroll
        for (int nt = 0; nt < 4; nt++)
            #pragma unroll
            for (int e = 0; e < 4; e++) acc[nt][e] = 0.f;

        const uint32_t xb = sb + XS_OFF + cur * XBUF_SZ;
        #pragma unroll
        for (int ks = 0; ks < 8; ks++) {
            uint32_t af[4], b0v[4], b1v[4];
            ldsm4(af, a_off + ks * 32);
            ldsm4(b0v, xb + b_off0 + ks * 32);
            ldsm4(b1v, xb + b_off1 + ks * 32);
            mma16816(acc[0], af, b0v[0], b0v[2]);
            mma16816(acc[1], af, b0v[1], b0v[3]);
            mma16816(acc[2], af, b1v[0], b1v[2]);
            mma16816(acc[3], af, b1v[1], b1v[3]);
        }

        const float* tsq_s = reinterpret_cast<const float*>(smem + TSQ_OFF + cur * 256);

        // ---- threshold fast-path: does any row need an insertion?
        bool f0 = false, f1 = false;
        #pragma unroll
        for (int nt = 0; nt < 4; nt++) {
            float tqa = tsq_s[wn * 32 + nt * 8 + (lane & 3) * 2 + 0];
            float tqb = tsq_s[wn * 32 + nt * 8 + (lane & 3) * 2 + 1];
            f0 |= (acc[nt][0] + tqa < thrA) | (acc[nt][1] + tqb < thrA);
            f1 |= (acc[nt][2] + tqa < thrB) | (acc[nt][3] + tqb < thrB);
        }
        unsigned bl0 = __ballot_sync(0xffffffffu, f0);
        unsigned bl1 = __ballot_sync(0xffffffffu, f1);
        if (!(bl0 | bl1)) continue;
        unsigned t0 = (bl0 | (bl0 >> 1) | (bl0 >> 2) | (bl0 >> 3)) & 0x11111111u;
        unsigned t1 = (bl1 | (bl1 >> 1) | (bl1 >> 2) | (bl1 >> 3)) & 0x11111111u;

        // stage 16q x 32c raw scores
        #pragma unroll
        for (int nt = 0; nt < 4; nt++)
            #pragma unroll
            for (int e = 0; e < 4; e++) {
                int r = r0 + (e >> 1) * 8;
                int c = nt * 8 + (lane & 3) * 2 + (e & 1);
                stg[r * 33 + c] = acc[nt][e];
            }
        __syncwarp();

        const float myt = tsq_s[wn * 32 + lane];
        const int cbase = sbase + i * CTILE + wn * 32;
        #pragma unroll 1
        for (int j = 0; j < 16; j++) {
            unsigned fl = (j < 8) ? (t0 >> (4 * j)) : (t1 >> (4 * (j - 8)));
            if (!(fl & 1u)) continue;
            float val = stg[j * 33 + lane] + myt;
            float thr = __shfl_sync(0xffffffffu, ld[j], 31);
            unsigned pass = __ballot_sync(0xffffffffu, val < thr);
            while (pass) {
                int src = __ffs(pass) - 1;
                pass &= pass - 1;
                float v  = __shfl_sync(0xffffffffu, val, src);
                int   gi = cbase + src;
                unsigned m = __ballot_sync(0xffffffffu, v < ld[j]);
                if (m) {
                    int p = __ffs(m) - 1;
                    float dn = __shfl_up_sync(0xffffffffu, ld[j], 1);
                    int   in = __shfl_up_sync(0xffffffffu, li[j], 1);
                    if (lane > p)       { ld[j] = dn; li[j] = in; }
                    else if (lane == p) { ld[j] = v;  li[j] = gi; }
                    thr = __shfl_sync(0xffffffffu, ld[j], 31);
                }
            }
            // refresh per-lane row thresholds (row j's new 32nd best)
            float nt_ = __shfl_sync(0xffffffffu, ld[j], 31);
            if (r0 == (j & 7)) {
                if (j < 8) thrA = nt_; else thrB = nt_;
            }
        }
        __syncwarp();
    }

    const int strip = split * 2 + wn;
    #pragma unroll
    for (int j = 0; j < 16; j++) {
        int q = qbase + wm * 16 + j;
        if (q < q_total)
            g_idx[(q * NSTRIP + strip) * KSEL + lane] = li[j];
    }
}

// ---------------------------------------------------------------- kernel 3
__global__ void __launch_bounds__(256, 4)
knn_refine(const float* __restrict__ Qm, const float* __restrict__ X,
           const float* __restrict__ y, float* __restrict__ out,
           int q_total, int n) {
    __shared__ __align__(16) float qsm[8][DDIM];
    const int lane = threadIdx.x & 31;
    const int warp = threadIdx.x >> 5;
    const int q = blockIdx.x * 8 + warp;
    if (q >= q_total) return;

    reinterpret_cast<float4*>(qsm[warp])[lane] =
        reinterpret_cast<const float4*>(Qm + (size_t)q * DDIM)[lane];
    __syncwarp();
    const float4* q4 = reinterpret_cast<const float4*>(qsm[warp]);

    float ld = CUDART_INF_F;
    int   li = 0;
    const int* ip = g_idx + (size_t)q * NSTRIP * KSEL;

    #pragma unroll 1
    for (int g = 0; g < NSTRIP; g++) {
        int idx = ip[g * KSEL + lane];
        if (idx >= n) idx = n - 1;
        const float4* xr = reinterpret_cast<const float4*>(X + (size_t)idx * DDIM);
        float a0 = 0.f, a1 = 0.f, a2 = 0.f, a3 = 0.f;
        #pragma unroll 8
        for (int kk = 0; kk < 32; kk++) {
            float4 xv = xr[kk];
            float4 qv = q4[kk];
            a0 = fmaf(qv.x, xv.x, a0);
            a1 = fmaf(qv.y, xv.y, a1);
            a2 = fmaf(qv.z, xv.z, a2);
            a3 = fmaf(qv.w, xv.w, a3);
        }
        float val = fmaf(-2.f, (a0 + a1) + (a2 + a3), g_tsq[idx]);
        int   vi  = idx;
        float thr = __shfl_sync(0xffffffffu, ld, 31);
        unsigned pass = __ballot_sync(0xffffffffu, val < thr);
        while (pass) {
            int src = __ffs(pass) - 1;
            pass &= pass - 1;
            float v  = __shfl_sync(0xffffffffu, val, src);
            int   gi = __shfl_sync(0xffffffffu, vi,  src);
            unsigned m = __ballot_sync(0xffffffffu, v < ld);
            if (m) {
                int p = __ffs(m) - 1;
                float dn = __shfl_up_sync(0xffffffffu, ld, 1);
                int   in = __shfl_up_sync(0xffffffffu, li, 1);
                if (lane > p)       { ld = dn; li = in; }
                else if (lane == p) { ld = v;  li = gi; }
                thr = __shfl_sync(0xffffffffu, ld, 31);
            }
        }
    }

    float yv = y[li];
    #pragma unroll
    for (int o = 16; o; o >>= 1) yv += __shfl_xor_sync(0xffffffffu, yv, o);
    if (lane == 0) out[q] = yv * (1.0f / (float)KSEL);
}

// ---------------------------------------------------------------- launcher
extern "C" void kernel_launch(void* const* d_in, const int* in_sizes, int n_in,
                              void* d_out, int out_size) {
    const float* Qm = (const float*)d_in[0];
    const float* X  = (const float*)d_in[1];
    const float* y  = (const float*)d_in[2];
    const int q_total = in_sizes[0] / DDIM;   // 4096
    const int n       = in_sizes[2];          // 100000
    float* out = (float*)d_out;

    split_kernel<<<NPAD / 8, 256>>>(X, n);

    static int smem_set = 0;
    if (!smem_set) {
        cudaFuncSetAttribute(knn_main, cudaFuncAttributeMaxDynamicSharedMemorySize,
                             SM_TOTAL);
        smem_set = 1;
    }
    dim3 grid((q_total + QTILE - 1) / QTILE, SPLITS);
    knn_main<<<grid, NTHR, SM_TOTAL>>>(Qm, q_total);

    knn_refine<<<(q_total + 7) / 8, 256>>>(Qm, X, y, out, q_total, n);
}

// round 10
// speedup vs baseline: 1.6579x; 1.6579x over previous
#include <cuda_runtime.h>
#include <cuda_fp16.h>
#include <math_constants.h>
#include <cstdint>

// KNN screen-then-refine, round 10 = round-7 inner loop verbatim, launch shape
// fixed: QTILE=64, 256 thr/CTA, 2 CTAs/SM, grid 64x4=256 (single wave).
//  K2: 1-pass fp16 mma screen, warp tile 16q x 32c, approx top-32 per
//      (query, 32c strip), 8 strips/query.
//  K3: exact fp32 refine of 256 survivors -> top-32 -> mean(y).
#define DDIM      128
#define QTILE     64
#define CTILE     64
#define SPLITS    4
#define NPAD      100352
#define PER_SPLIT (NPAD / SPLITS)      // 25088
#define CHUNKS    (PER_SPLIT / CTILE)  // 392
#define NSTRIP    8                    // 4 splits * 2 c-strips
#define KSEL      32
#define QMAX      4096
#define NTHR      256

#define QSTR      136                  // padded row stride in halfs
#define QS_OFF    0                    // 64*136*2 = 17408
#define XS_OFF    17408                // 2 bufs * 64*136*2 = 34816
#define XBUF_SZ   17408
#define TSQ_OFF   52224                // 2 * 256
#define STAGE_OFF 52736                // 8 warps * 16*33*4 = 16896
#define SM_TOTAL  69632

__device__ __align__(16) __half g_xh[(size_t)NPAD * DDIM];
__device__ __align__(16) float  g_tsq[NPAD];
__device__ int g_idx[QMAX * NSTRIP * KSEL];

__device__ __forceinline__ uint32_t smem_u32(const void* p) {
    uint32_t a;
    asm("{ .reg .u64 t; cvta.to.shared.u64 t, %1; cvt.u32.u64 %0, t; }" : "=r"(a) : "l"(p));
    return a;
}
#define CPA16(dst, src) \
    asm volatile("cp.async.cg.shared.global [%0], [%1], 16;" :: "r"(dst), "l"(src))
#define CPA_COMMIT() asm volatile("cp.async.commit_group;" ::: "memory")

__device__ __forceinline__ void ldsm4(uint32_t* r, uint32_t a) {
    asm volatile("ldmatrix.sync.aligned.m8n8.x4.shared.b16 {%0,%1,%2,%3}, [%4];"
                 : "=r"(r[0]), "=r"(r[1]), "=r"(r[2]), "=r"(r[3]) : "r"(a));
}
__device__ __forceinline__ void mma16816(float* d, const uint32_t* a,
                                         uint32_t b0, uint32_t b1) {
    asm volatile("mma.sync.aligned.m16n8k16.row.col.f32.f16.f16.f32 "
                 "{%0,%1,%2,%3}, {%4,%5,%6,%7}, {%8,%9}, {%0,%1,%2,%3};"
                 : "+f"(d[0]), "+f"(d[1]), "+f"(d[2]), "+f"(d[3])
                 : "r"(a[0]), "r"(a[1]), "r"(a[2]), "r"(a[3]), "r"(b0), "r"(b1));
}
__device__ __forceinline__ uint32_t pkh(__half a, __half b) {
    __half2 t = __halves2half2(a, b);
    return *reinterpret_cast<uint32_t*>(&t);
}

// ---------------------------------------------------------------- kernel 1
__global__ void split_kernel(const float* __restrict__ X, int n) {
    int row  = blockIdx.x * 8 + (threadIdx.x >> 5);
    int lane = threadIdx.x & 31;
    if (row >= NPAD) return;
    size_t base = (size_t)row * DDIM + lane * 4;
    if (row < n) {
        float4 v = reinterpret_cast<const float4*>(X + (size_t)row * DDIM)[lane];
        float ss = v.x * v.x + v.y * v.y + v.z * v.z + v.w * v.w;
        #pragma unroll
        for (int o = 16; o; o >>= 1) ss += __shfl_xor_sync(0xffffffffu, ss, o);
        if (lane == 0) g_tsq[row] = ss;
        *reinterpret_cast<uint2*>(g_xh + base) =
            make_uint2(pkh(__float2half_rn(v.x), __float2half_rn(v.y)),
                       pkh(__float2half_rn(v.z), __float2half_rn(v.w)));
    } else {
        if (lane == 0) g_tsq[row] = CUDART_INF_F;
        *reinterpret_cast<uint2*>(g_xh + base) = make_uint2(0u, 0u);
    }
}

// ---------------------------------------------------------------- loader
// 64 rows * 256B/row = 1024 x 16B transfers -> 4 per thread; + tsq 256B.
__device__ __forceinline__ void load_chunk(uint32_t sb, int cb, int buf, int tid) {
    #pragma unroll
    for (int t = 0; t < 4; t++) {
        int idx = t * NTHR + tid;
        int row = idx >> 4, c16 = idx & 15;
        const char* sp = reinterpret_cast<const char*>(
            g_xh + (size_t)(cb + row) * DDIM) + c16 * 16;
        CPA16(sb + XS_OFF + buf * XBUF_SZ + (uint32_t)(row * QSTR * 2 + c16 * 16), sp);
    }
    if (tid < 16) {
        const char* tp = reinterpret_cast<const char*>(g_tsq + cb) + tid * 16;
        CPA16(sb + TSQ_OFF + buf * 256 + tid * 16, tp);
    }
    CPA_COMMIT();
}

// ---------------------------------------------------------------- kernel 2
__global__ void __launch_bounds__(NTHR, 2)
knn_main(const float* __restrict__ Qm, int q_total) {
    extern __shared__ char smem[];
    uint32_t sb = smem_u32(smem);
    const int tid  = threadIdx.x;
    const int lane = tid & 31;
    const int warp = tid >> 5;
    const int wm   = warp >> 1;          // 0..3 : q strip of 16
    const int wn   = warp & 1;           // 0..1 : c strip of 32
    const int split = blockIdx.y;
    const int qbase = blockIdx.x * QTILE;
    const int sbase = split * PER_SPLIT;

    load_chunk(sb, sbase, 0, tid);       // chunk 0 in flight

    // Q (-2x, fp16) -> smem
    __half* qs = reinterpret_cast<__half*>(smem + QS_OFF);
    for (int i = tid; i < QTILE * DDIM; i += NTHR) {
        int row = i >> 7, k = i & 127;
        int q = qbase + row; if (q >= q_total) q = q_total - 1;
        qs[row * QSTR + k] = __float2half_rn(-2.f * Qm[(size_t)q * DDIM + k]);
    }

    float ld[16]; int li[16];
    #pragma unroll
    for (int j = 0; j < 16; j++) { ld[j] = CUDART_INF_F; li[j] = 0; }

    const uint32_t a_off = sb + QS_OFF
        + (uint32_t)((wm * 16 + (lane & 15)) * QSTR + (lane >> 4) * 8) * 2;
    const uint32_t b_off0 = (uint32_t)((wn * 32 + (lane & 15)) * QSTR + (lane >> 4) * 8) * 2;
    const uint32_t b_off1 = b_off0 + (uint32_t)(16 * QSTR * 2);
    float* stg = reinterpret_cast<float*>(smem + STAGE_OFF) + warp * (16 * 33);

    for (int i = 0; i < CHUNKS; i++) {
        const int cur = i & 1, nb = cur ^ 1;
        if (i + 1 < CHUNKS) {
            load_chunk(sb, sbase + (i + 1) * CTILE, nb, tid);
            asm volatile("cp.async.wait_group 1;" ::: "memory");
        } else {
            asm volatile("cp.async.wait_group 0;" ::: "memory");
        }
        __syncthreads();

        float acc[4][4];
        #pragma unroll
        for (int nt = 0; nt < 4; nt++)
            #pragma unroll
            for (int e = 0; e < 4; e++) acc[nt][e] = 0.f;

        const uint32_t xb = sb + XS_OFF + cur * XBUF_SZ;
        #pragma unroll
        for (int ks = 0; ks < 8; ks++) {
            uint32_t af[4], b0v[4], b1v[4];
            ldsm4(af, a_off + ks * 32);
            ldsm4(b0v, xb + b_off0 + ks * 32);
            ldsm4(b1v, xb + b_off1 + ks * 32);
            mma16816(acc[0], af, b0v[0], b0v[2]);
            mma16816(acc[1], af, b0v[1], b0v[3]);
            mma16816(acc[2], af, b1v[0], b1v[2]);
            mma16816(acc[3], af, b1v[1], b1v[3]);
        }

        // stage 16q x 32c scores
        #pragma unroll
        for (int nt = 0; nt < 4; nt++)
            #pragma unroll
            for (int e = 0; e < 4; e++) {
                int r = (lane >> 2) + (e >> 1) * 8;
                int c = nt * 8 + (lane & 3) * 2 + (e & 1);
                stg[r * 33 + c] = acc[nt][e];
            }
        __syncwarp();

        const float myt = reinterpret_cast<const float*>(smem + TSQ_OFF + cur * 256)
                              [wn * 32 + lane];
        const int cbase = sbase + i * CTILE + wn * 32;
        #pragma unroll
        for (int j = 0; j < 16; j++) {
            float val = stg[j * 33 + lane] + myt;
            float thr = __shfl_sync(0xffffffffu, ld[j], 31);
            unsigned pass = __ballot_sync(0xffffffffu, val < thr);
            while (pass) {
                int src = __ffs(pass) - 1;
                pass &= pass - 1;
                float v  = __shfl_sync(0xffffffffu, val, src);
                int   gi = cbase + src;
                unsigned m = __ballot_sync(0xffffffffu, v < ld[j]);
                if (m) {
                    int p = __ffs(m) - 1;
                    float dn = __shfl_up_sync(0xffffffffu, ld[j], 1);
                    int   in = __shfl_up_sync(0xffffffffu, li[j], 1);
                    if (lane > p)       { ld[j] = dn; li[j] = in; }
                    else if (lane == p) { ld[j] = v;  li[j] = gi; }
                    thr = __shfl_sync(0xffffffffu, ld[j], 31);
                }
            }
        }
        __syncthreads();
    }

    const int strip = split * 2 + wn;
    #pragma unroll
    for (int j = 0; j < 16; j++) {
        int q = qbase + wm * 16 + j;
        if (q < q_total)
            g_idx[(q * NSTRIP + strip) * KSEL + lane] = li[j];
    }
}

// ---------------------------------------------------------------- kernel 3
__global__ void __launch_bounds__(256, 4)
knn_refine(const float* __restrict__ Qm, const float* __restrict__ X,
           const float* __restrict__ y, float* __restrict__ out,
           int q_total, int n) {
    __shared__ __align__(16) float qsm[8][DDIM];
    const int lane = threadIdx.x & 31;
    const int warp = threadIdx.x >> 5;
    const int q = blockIdx.x * 8 + warp;
    if (q >= q_total) return;

    reinterpret_cast<float4*>(qsm[warp])[lane] =
        reinterpret_cast<const float4*>(Qm + (size_t)q * DDIM)[lane];
    __syncwarp();
    const float4* q4 = reinterpret_cast<const float4*>(qsm[warp]);

    float ld = CUDART_INF_F;
    int   li = 0;
    const int* ip = g_idx + (size_t)q * NSTRIP * KSEL;

    #pragma unroll 1
    for (int g = 0; g < NSTRIP; g++) {
        int idx = ip[g * KSEL + lane];
        if (idx >= n) idx = n - 1;
        const float4* xr = reinterpret_cast<const float4*>(X + (size_t)idx * DDIM);
        float a0 = 0.f, a1 = 0.f, a2 = 0.f, a3 = 0.f;
        #pragma unroll 8
        for (int kk = 0; kk < 32; kk++) {
            float4 xv = xr[kk];
            float4 qv = q4[kk];
            a0 = fmaf(qv.x, xv.x, a0);
            a1 = fmaf(qv.y, xv.y, a1);
            a2 = fmaf(qv.z, xv.z, a2);
            a3 = fmaf(qv.w, xv.w, a3);
        }
        float val = fmaf(-2.f, (a0 + a1) + (a2 + a3), g_tsq[idx]);
        int   vi  = idx;
        float thr = __shfl_sync(0xffffffffu, ld, 31);
        unsigned pass = __ballot_sync(0xffffffffu, val < thr);
        while (pass) {
            int src = __ffs(pass) - 1;
            pass &= pass - 1;
            float v  = __shfl_sync(0xffffffffu, val, src);
            int   gi = __shfl_sync(0xffffffffu, vi,  src);
            unsigned m = __ballot_sync(0xffffffffu, v < ld);
            if (m) {
                int p = __ffs(m) - 1;
                float dn = __shfl_up_sync(0xffffffffu, ld, 1);
                int   in = __shfl_up_sync(0xffffffffu, li, 1);
                if (lane > p)       { ld = dn; li = in; }
                else if (lane == p) { ld = v;  li = gi; }
                thr = __shfl_sync(0xffffffffu, ld, 31);
            }
        }
    }

    float yv = y[li];
    #pragma unroll
    for (int o = 16; o; o >>= 1) yv += __shfl_xor_sync(0xffffffffu, yv, o);
    if (lane == 0) out[q] = yv * (1.0f / (float)KSEL);
}

// ---------------------------------------------------------------- launcher
extern "C" void kernel_launch(void* const* d_in, const int* in_sizes, int n_in,
                              void* d_out, int out_size) {
    const float* Qm = (const float*)d_in[0];
    const float* X  = (const float*)d_in[1];
    const float* y  = (const float*)d_in[2];
    const int q_total = in_sizes[0] / DDIM;   // 4096
    const int n       = in_sizes[2];          // 100000
    float* out = (float*)d_out;

    split_kernel<<<NPAD / 8, 256>>>(X, n);

    static int smem_set = 0;
    if (!smem_set) {
        cudaFuncSetAttribute(knn_main, cudaFuncAttributeMaxDynamicSharedMemorySize,
                             SM_TOTAL);
        smem_set = 1;
    }
    dim3 grid((q_total + QTILE - 1) / QTILE, SPLITS);
    knn_main<<<grid, NTHR, SM_TOTAL>>>(Qm, q_total);

    knn_refine<<<(q_total + 7) / 8, 256>>>(Qm, X, y, out, q_total, n);
}